// round 1
// baseline (speedup 1.0000x reference)
#include <cuda_runtime.h>
#include <math.h>

#define N_TOK 1024
#define TOPK  2
#define NEXP  16
#define HID   1024
#define DIM   2048
#define RNK   16
#define NKTOT (N_TOK*TOPK)
#define LSCALE 0.25f

#define TMU 64
#define KB  8

// ---------------- scratch (static device globals; no allocation) ----------------
__device__ int   g_cnt[NEXP];
__device__ int   g_list[NEXP*NKTOT];
__device__ float g_t[NKTOT*RNK];                 // up-lora  t  = x   @ up_a^T
__device__ float g_t2[NKTOT*RNK];                // down-lora t2 = act @ down_a^T
__device__ float g_act[(size_t)NKTOT*HID];       // gelu(up1)*up2 per (n,k)
__device__ float g_down[(size_t)NKTOT*DIM];      // per (n,k) down output

// ---------------- routing ----------------
__global__ void k_zero() {
    if (threadIdx.x < NEXP) g_cnt[threadIdx.x] = 0;
}

__global__ void k_route(const int* __restrict__ ids) {
    int nk = blockIdx.x*blockDim.x + threadIdx.x;
    if (nk < NKTOT) {
        int e = ids[nk];
        int p = atomicAdd(&g_cnt[e], 1);
        g_list[e*NKTOT + p] = nk;
    }
}

// ---------------- LoRA t vectors ----------------
// g_t[nk][r] = dot(x[n], up_a[e][r])   (one block per nk, 4 warps x 4 r)
__global__ void k_t_up(const float* __restrict__ x, const int* __restrict__ ids,
                       const float* __restrict__ up_a) {
    int nk = blockIdx.x;
    int n  = nk / TOPK;
    int e  = ids[nk];
    int warp = threadIdx.x >> 5, lane = threadIdx.x & 31;
    const float4* xr = (const float4*)(x + (size_t)n*DIM);
    const float4* A  = (const float4*)(up_a + (size_t)e*RNK*DIM);
    #pragma unroll
    for (int rr = 0; rr < 4; rr++) {
        int r = warp*4 + rr;
        const float4* ar = A + (size_t)r*(DIM/4);
        float s = 0.f;
        for (int i = lane; i < DIM/4; i += 32) {
            float4 xv = xr[i], av = ar[i];
            s += xv.x*av.x + xv.y*av.y + xv.z*av.z + xv.w*av.w;
        }
        #pragma unroll
        for (int o = 16; o > 0; o >>= 1) s += __shfl_xor_sync(0xffffffffu, s, o);
        if (lane == 0) g_t[nk*RNK + r] = s;
    }
}

// g_t2[nk][r] = dot(g_act[nk], down_a[e][r])
__global__ void k_t_down(const int* __restrict__ ids, const float* __restrict__ down_a) {
    int nk = blockIdx.x;
    int e  = ids[nk];
    int warp = threadIdx.x >> 5, lane = threadIdx.x & 31;
    const float4* xr = (const float4*)(g_act + (size_t)nk*HID);
    const float4* A  = (const float4*)(down_a + (size_t)e*RNK*HID);
    #pragma unroll
    for (int rr = 0; rr < 4; rr++) {
        int r = warp*4 + rr;
        const float4* ar = A + (size_t)r*(HID/4);
        float s = 0.f;
        for (int i = lane; i < HID/4; i += 32) {
            float4 xv = xr[i], av = ar[i];
            s += xv.x*av.x + xv.y*av.y + xv.z*av.z + xv.w*av.w;
        }
        #pragma unroll
        for (int o = 16; o > 0; o >>= 1) s += __shfl_xor_sync(0xffffffffu, s, o);
        if (lane == 0) g_t2[nk*RNK + r] = s;
    }
}

// ---------------- up GEMM + LoRA + gelu*mul ----------------
// Block: 64 token-rows of expert e, 64 "jj" column pairs (u1 = w_up row j0+jj,
// u2 = w_up row H+j0+jj interleaved as smem column c = 2*jj + half).
__global__ __launch_bounds__(256, 2)
void k_up(const float* __restrict__ x,
          const float* __restrict__ w_up,
          const float* __restrict__ up_b) {
    int e   = blockIdx.z;
    int cnt = g_cnt[e];
    int m0  = blockIdx.y * TMU;
    if (m0 >= cnt) return;
    int j0  = blockIdx.x * 64;

    __shared__ float As[KB][TMU];
    __shared__ float Bs[KB][128];
    __shared__ int   ls_nk[TMU];
    __shared__ int   ls_n[TMU];
    __shared__ float t_sm[TMU][RNK];

    int tid = threadIdx.x;
    if (tid < TMU) {
        int m  = m0 + tid;
        int nk = g_list[e*NKTOT + ((m < cnt) ? m : 0)];
        ls_nk[tid] = nk;
        ls_n[tid]  = nk / TOPK;
    }
    __syncthreads();
    for (int i = tid; i < TMU*RNK; i += 256)
        t_sm[i / RNK][i % RNK] = g_t[ls_nk[i / RNK]*RNK + (i % RNK)];

    const float* W = w_up + (size_t)e*(2*HID)*(size_t)DIM;

    int warp = tid >> 5, lane = tid & 31;
    int warp_m = warp & 1, warp_n = warp >> 1;      // 2 x 4 warp grid
    int lane_m = lane & 7, lane_n = lane >> 3;      // 8 x 4 lane grid
    int row0 = warp_m*32 + lane_m*4;
    int col0 = warp_n*32 + lane_n*8;

    int koff  = (tid & 1) * 4;
    int a_row = tid >> 1;                           // valid when tid < 128
    const float* a_ptr = x + (size_t)ls_n[a_row & (TMU-1)]*DIM + koff;
    int b_r    = tid >> 1;
    int b_jj   = b_r >> 1;
    int b_half = b_r & 1;
    const float* b_ptr = W + (size_t)((b_half ? HID : 0) + j0 + b_jj)*DIM + koff;

    float acc[4][8];
    #pragma unroll
    for (int i = 0; i < 4; i++)
        #pragma unroll
        for (int j = 0; j < 8; j++) acc[i][j] = 0.f;

    float4 av = make_float4(0.f,0.f,0.f,0.f), bv;
    if (tid < 128) av = *(const float4*)(a_ptr);
    bv = *(const float4*)(b_ptr);

    for (int k0 = 0; k0 < DIM; k0 += KB) {
        if (tid < 128) {
            As[koff+0][a_row]=av.x; As[koff+1][a_row]=av.y;
            As[koff+2][a_row]=av.z; As[koff+3][a_row]=av.w;
        }
        Bs[koff+0][b_r]=bv.x; Bs[koff+1][b_r]=bv.y;
        Bs[koff+2][b_r]=bv.z; Bs[koff+3][b_r]=bv.w;
        __syncthreads();
        int kn = (k0 + KB < DIM) ? (k0 + KB) : 0;   // prefetch next stage
        if (tid < 128) av = *(const float4*)(a_ptr + kn);
        bv = *(const float4*)(b_ptr + kn);
        #pragma unroll
        for (int k = 0; k < KB; k++) {
            float4 a  = *(const float4*)&As[k][row0];
            float4 b0 = *(const float4*)&Bs[k][col0];
            float4 b1 = *(const float4*)&Bs[k][col0+4];
            float ar[4] = {a.x, a.y, a.z, a.w};
            float br[8] = {b0.x,b0.y,b0.z,b0.w,b1.x,b1.y,b1.z,b1.w};
            #pragma unroll
            for (int i = 0; i < 4; i++)
                #pragma unroll
                for (int j = 0; j < 8; j++) acc[i][j] += ar[i]*br[j];
        }
        __syncthreads();
    }

    // epilogue: LoRA rank-16 update + exact gelu * mul
    const float* Bup = up_b + (size_t)e*(2*HID)*RNK;
    #pragma unroll
    for (int p = 0; p < 4; p++) {
        int jj   = (col0 >> 1) + p;
        int jcol = j0 + jj;
        float bu0[16], bu1[16];
        const float4* p0 = (const float4*)(Bup + (size_t)jcol*RNK);
        const float4* p1 = (const float4*)(Bup + (size_t)(HID + jcol)*RNK);
        #pragma unroll
        for (int q = 0; q < 4; q++) { ((float4*)bu0)[q] = p0[q]; ((float4*)bu1)[q] = p1[q]; }
        #pragma unroll
        for (int i = 0; i < 4; i++) {
            int m = row0 + i;
            if (m0 + m < cnt) {
                float l0 = 0.f, l1 = 0.f;
                #pragma unroll
                for (int r = 0; r < RNK; r++) { l0 += t_sm[m][r]*bu0[r]; l1 += t_sm[m][r]*bu1[r]; }
                float u1 = acc[i][2*p]   + LSCALE*l0;
                float u2 = acc[i][2*p+1] + LSCALE*l1;
                float g  = 0.5f*u1*(1.0f + erff(u1*0.7071067811865476f));
                g_act[(size_t)ls_nk[m]*HID + jcol] = g*u2;
            }
        }
    }
}

// ---------------- down GEMM + LoRA + routed-weight, per-(n,k) output ----------------
__global__ __launch_bounds__(256, 2)
void k_down(const float* __restrict__ tw,
            const float* __restrict__ w_down,
            const float* __restrict__ down_b) {
    int e   = blockIdx.z;
    int cnt = g_cnt[e];
    int m0  = blockIdx.y * TMU;
    if (m0 >= cnt) return;
    int d0  = blockIdx.x * 128;

    __shared__ float As[KB][TMU];
    __shared__ float Bs[KB][128];
    __shared__ int   ls_nk[TMU];
    __shared__ float t_sm[TMU][RNK];
    __shared__ float tw_sm[TMU];

    int tid = threadIdx.x;
    if (tid < TMU) {
        int m  = m0 + tid;
        int nk = g_list[e*NKTOT + ((m < cnt) ? m : 0)];
        ls_nk[tid] = nk;
        tw_sm[tid] = tw[nk];
    }
    __syncthreads();
    for (int i = tid; i < TMU*RNK; i += 256)
        t_sm[i / RNK][i % RNK] = g_t2[ls_nk[i / RNK]*RNK + (i % RNK)];

    const float* W = w_down + (size_t)e*DIM*(size_t)HID;

    int warp = tid >> 5, lane = tid & 31;
    int warp_m = warp & 1, warp_n = warp >> 1;
    int lane_m = lane & 7, lane_n = lane >> 3;
    int row0 = warp_m*32 + lane_m*4;
    int col0 = warp_n*32 + lane_n*8;

    int koff  = (tid & 1) * 4;
    int a_row = tid >> 1;
    const float* a_ptr = g_act + (size_t)ls_nk[a_row & (TMU-1)]*HID + koff;
    int b_r = tid >> 1;
    const float* b_ptr = W + (size_t)(d0 + b_r)*HID + koff;

    float acc[4][8];
    #pragma unroll
    for (int i = 0; i < 4; i++)
        #pragma unroll
        for (int j = 0; j < 8; j++) acc[i][j] = 0.f;

    float4 av = make_float4(0.f,0.f,0.f,0.f), bv;
    if (tid < 128) av = *(const float4*)(a_ptr);
    bv = *(const float4*)(b_ptr);

    for (int k0 = 0; k0 < HID; k0 += KB) {
        if (tid < 128) {
            As[koff+0][a_row]=av.x; As[koff+1][a_row]=av.y;
            As[koff+2][a_row]=av.z; As[koff+3][a_row]=av.w;
        }
        Bs[koff+0][b_r]=bv.x; Bs[koff+1][b_r]=bv.y;
        Bs[koff+2][b_r]=bv.z; Bs[koff+3][b_r]=bv.w;
        __syncthreads();
        int kn = (k0 + KB < HID) ? (k0 + KB) : 0;
        if (tid < 128) av = *(const float4*)(a_ptr + kn);
        bv = *(const float4*)(b_ptr + kn);
        #pragma unroll
        for (int k = 0; k < KB; k++) {
            float4 a  = *(const float4*)&As[k][row0];
            float4 b0 = *(const float4*)&Bs[k][col0];
            float4 b1 = *(const float4*)&Bs[k][col0+4];
            float ar[4] = {a.x, a.y, a.z, a.w};
            float br[8] = {b0.x,b0.y,b0.z,b0.w,b1.x,b1.y,b1.z,b1.w};
            #pragma unroll
            for (int i = 0; i < 4; i++)
                #pragma unroll
                for (int j = 0; j < 8; j++) acc[i][j] += ar[i]*br[j];
        }
        __syncthreads();
    }

    const float* Bdn = down_b + (size_t)e*DIM*RNK;
    #pragma unroll
    for (int ci = 0; ci < 8; ci++) {
        int d = d0 + col0 + ci;
        float bd[16];
        const float4* pd = (const float4*)(Bdn + (size_t)d*RNK);
        #pragma unroll
        for (int q = 0; q < 4; q++) ((float4*)bd)[q] = pd[q];
        #pragma unroll
        for (int i = 0; i < 4; i++) {
            int m = row0 + i;
            if (m0 + m < cnt) {
                float l = 0.f;
                #pragma unroll
                for (int r = 0; r < RNK; r++) l += t_sm[m][r]*bd[r];
                g_down[(size_t)ls_nk[m]*DIM + d] = (acc[i][ci] + LSCALE*l) * tw_sm[m];
            }
        }
    }
}

// ---------------- deterministic k-sum ----------------
__global__ void k_combine(float* __restrict__ out) {
    int idx = blockIdx.x*blockDim.x + threadIdx.x;   // float4 index
    if (idx < N_TOK*DIM/4) {
        int n    = idx / (DIM/4);
        int rest = idx - n*(DIM/4);
        const float4* a = (const float4*)g_down + (size_t)(2*n)*(DIM/4) + rest;
        const float4* b = a + (DIM/4);
        float4 va = *a, vb = *b;
        float4 r = make_float4(va.x+vb.x, va.y+vb.y, va.z+vb.z, va.w+vb.w);
        ((float4*)out)[idx] = r;
    }
}

// ---------------- launch ----------------
extern "C" void kernel_launch(void* const* d_in, const int* in_sizes, int n_in,
                              void* d_out, int out_size) {
    const float* x      = (const float*)d_in[0];
    const float* tw     = (const float*)d_in[1];
    const int*   ids    = (const int*)  d_in[2];
    const float* w_up   = (const float*)d_in[3];
    const float* w_down = (const float*)d_in[4];
    const float* up_a   = (const float*)d_in[5];
    const float* up_b   = (const float*)d_in[6];
    const float* down_a = (const float*)d_in[7];
    const float* down_b = (const float*)d_in[8];
    float* out = (float*)d_out;
    (void)in_sizes; (void)n_in; (void)out_size;

    k_zero<<<1, 32>>>();
    k_route<<<(NKTOT+255)/256, 256>>>(ids);
    k_t_up<<<NKTOT, 128>>>(x, ids, up_a);
    k_up<<<dim3(HID/64, NKTOT/TMU, NEXP), 256>>>(x, w_up, up_b);
    k_t_down<<<NKTOT, 128>>>(ids, down_a);
    k_down<<<dim3(DIM/128, NKTOT/TMU, NEXP), 256>>>(tw, w_down, down_b);
    k_combine<<<(N_TOK*DIM/4 + 255)/256, 256>>>(out);
}

// round 3
// speedup vs baseline: 1.9420x; 1.9420x over previous
#include <cuda_runtime.h>
#include <math.h>
#include <cstdint>

#define N_TOK 1024
#define TOPK  2
#define NEXP  16
#define HID   1024
#define DIM   2048
#define RNK   16
#define NKTOT (N_TOK*TOPK)
#define LSCALE 0.25f

// ---------------- scratch (static device globals; no allocation) ----------------
__device__ int   g_cnt[NEXP];
__device__ int   g_list[NEXP*NKTOT];
__device__ __align__(16) float g_t[NKTOT*RNK];
__device__ __align__(16) float g_t2[NKTOT*RNK];
__device__ __align__(16) float g_act[(size_t)NKTOT*HID];
__device__ __align__(16) float g_down[(size_t)NKTOT*DIM];

// ---------------- helpers ----------------
__device__ __forceinline__ float totf(float x){
    uint32_t u; asm("cvt.rna.tf32.f32 %0, %1;" : "=r"(u) : "f"(x));
    return __uint_as_float(u);
}
__device__ __forceinline__ float4 cv4(float4 v){
    return make_float4(totf(v.x), totf(v.y), totf(v.z), totf(v.w));
}
// smem float index for element (row, k) in a [rows][32]-float K-major tile,
// XOR-swizzled at float4 granularity: phys_q = q ^ (row & 7)
__device__ __forceinline__ int swz(int row, int k){
    return (row << 5) + ((((k >> 2) ^ row) & 7) << 2) + (k & 3);
}
__device__ __forceinline__ void mma8(float* c, const uint32_t* a, const uint32_t* b){
    asm volatile("mma.sync.aligned.m16n8k8.row.col.f32.tf32.tf32.f32 "
        "{%0,%1,%2,%3}, {%4,%5,%6,%7}, {%8,%9}, {%0,%1,%2,%3};"
        : "+f"(c[0]), "+f"(c[1]), "+f"(c[2]), "+f"(c[3])
        : "r"(a[0]), "r"(a[1]), "r"(a[2]), "r"(a[3]), "r"(b[0]), "r"(b[1]));
}

// smem layout (dynamic)
#define ASTG 16384u
#define BSTG 8192u
#define A_OFF 0u
#define B_OFF 32768u
#define LB_OFF 49152u
#define T_OFF 53248u
#define LS_OFF 61440u
#define TW_OFF 61952u
#define SMEM_BYTES 62464
#define STG_STRIDE 66           // epilogue stage row stride in floats

// ---------------- routing ----------------
__global__ void k_zero() { if (threadIdx.x < NEXP) g_cnt[threadIdx.x] = 0; }

__global__ void k_route(const int* __restrict__ ids) {
    int nk = blockIdx.x*blockDim.x + threadIdx.x;
    if (nk < NKTOT) {
        int e = ids[nk];
        int p = atomicAdd(&g_cnt[e], 1);
        g_list[e*NKTOT + p] = nk;
    }
}

// ---------------- LoRA t vectors ----------------
__global__ void k_t_up(const float* __restrict__ x, const int* __restrict__ ids,
                       const float* __restrict__ up_a) {
    int nk = blockIdx.x;
    int n  = nk / TOPK;
    int e  = ids[nk];
    int warp = threadIdx.x >> 5, lane = threadIdx.x & 31;
    const float4* xr = (const float4*)(x + (size_t)n*DIM);
    const float4* A  = (const float4*)(up_a + (size_t)e*RNK*DIM);
    #pragma unroll
    for (int rr = 0; rr < 4; rr++) {
        int r = warp*4 + rr;
        const float4* ar = A + (size_t)r*(DIM/4);
        float s = 0.f;
        for (int i = lane; i < DIM/4; i += 32) {
            float4 xv = xr[i], av = ar[i];
            s += xv.x*av.x + xv.y*av.y + xv.z*av.z + xv.w*av.w;
        }
        #pragma unroll
        for (int o = 16; o > 0; o >>= 1) s += __shfl_xor_sync(0xffffffffu, s, o);
        if (lane == 0) g_t[nk*RNK + r] = s;
    }
}

__global__ void k_t_down(const int* __restrict__ ids, const float* __restrict__ down_a) {
    int nk = blockIdx.x;
    int e  = ids[nk];
    int warp = threadIdx.x >> 5, lane = threadIdx.x & 31;
    const float4* xr = (const float4*)(g_act + (size_t)nk*HID);
    const float4* A  = (const float4*)(down_a + (size_t)e*RNK*HID);
    #pragma unroll
    for (int rr = 0; rr < 4; rr++) {
        int r = warp*4 + rr;
        const float4* ar = A + (size_t)r*(HID/4);
        float s = 0.f;
        for (int i = lane; i < HID/4; i += 32) {
            float4 xv = xr[i], av = ar[i];
            s += xv.x*av.x + xv.y*av.y + xv.z*av.z + xv.w*av.w;
        }
        #pragma unroll
        for (int o = 16; o > 0; o >>= 1) s += __shfl_xor_sync(0xffffffffu, s, o);
        if (lane == 0) g_t2[nk*RNK + r] = s;
    }
}

// ---------------- up GEMM (tf32 mma.sync) + LoRA + gelu*mul ----------------
// CTA: 128 token rows of expert e, 32 output pairs. D cols [0,32)=u1 rows
// j0..j0+31 of w_up, cols [32,64)=u2 rows HID+j0..  j0 = blockIdx.x*32.
__global__ __launch_bounds__(256, 2)
void k_up_tc(const float* __restrict__ x, const float* __restrict__ w_up,
             const float* __restrict__ up_b) {
    int e = blockIdx.z, cnt = g_cnt[e];
    int m0 = blockIdx.y * 128;
    if (m0 >= cnt) return;
    int j0 = blockIdx.x * 32;

    extern __shared__ __align__(16) char sm[];
    int tid = threadIdx.x, wid = tid >> 5, lid = tid & 31;

    int* ls = (int*)(sm + LS_OFF);
    if (tid < 128) {
        int m = m0 + tid;
        ls[tid] = g_list[e*NKTOT + ((m < cnt) ? m : 0)];
    }
    __syncthreads();

    float* tsm = (float*)(sm + T_OFF);
    float* lb  = (float*)(sm + LB_OFF);
    {
        const float* Bup = up_b + (size_t)e*(2*HID)*RNK;
        // t: 128*16 floats = 512 float4 (2/thread); lb: 64*16 = 256 float4 (1/thread)
        #pragma unroll
        for (int q = 0; q < 2; q++) {
            int f = tid*2 + q;
            int row = f >> 2, r4 = f & 3;
            ((float4*)tsm)[f] = ((const float4*)(g_t + (size_t)ls[row]*RNK))[r4];
        }
        int row = tid >> 2, r4 = tid & 3;
        int grow = (row < 32) ? (j0 + row) : (HID + j0 + row - 32);
        ((float4*)lb)[tid] = ((const float4*)(Bup + (size_t)grow*RNK))[r4];
    }
    __syncthreads();

    // producers
    int a_row = tid >> 1, a_seg = tid & 1;
    const float* ap = x + (size_t)(ls[a_row] >> 1)*DIM + a_seg*16;
    const float* W  = w_up + (size_t)e*(2*HID)*(size_t)DIM;
    int b_row = tid >> 2, b_seg = tid & 3;
    int bgrow = (b_row < 32) ? (j0 + b_row) : (HID + j0 + b_row - 32);
    const float* bp = W + (size_t)bgrow*DIM + b_seg*8;

    // preload chunk 0
    float4 va[4], vb[2];
    #pragma unroll
    for (int q = 0; q < 4; q++) va[q] = ((const float4*)ap)[q];
    #pragma unroll
    for (int q = 0; q < 2; q++) vb[q] = ((const float4*)bp)[q];
    {
        float* As = (float*)(sm + A_OFF);
        float* Bs = (float*)(sm + B_OFF);
        #pragma unroll
        for (int q = 0; q < 4; q++)
            ((float4*)As)[(a_row<<3) + ((a_seg*4 + q) ^ (a_row & 7))] = cv4(va[q]);
        #pragma unroll
        for (int q = 0; q < 2; q++)
            ((float4*)Bs)[(b_row<<3) + ((b_seg*2 + q) ^ (b_row & 7))] = cv4(vb[q]);
    }
    __syncthreads();

    int warp_m = wid & 3, warp_n = wid >> 2;
    int g = lid >> 2, t = lid & 3;
    float acc[2][4][4];
    #pragma unroll
    for (int mi = 0; mi < 2; mi++)
        #pragma unroll
        for (int ni = 0; ni < 4; ni++)
            #pragma unroll
            for (int q = 0; q < 4; q++) acc[mi][ni][q] = 0.f;

    const int NC = DIM/32;
    for (int c = 0; c < NC; c++) {
        int s = c & 1;
        if (c + 1 < NC) {
            #pragma unroll
            for (int q = 0; q < 4; q++) va[q] = ((const float4*)(ap + (c+1)*32))[q];
            #pragma unroll
            for (int q = 0; q < 2; q++) vb[q] = ((const float4*)(bp + (c+1)*32))[q];
        }
        const uint32_t* As = (const uint32_t*)(sm + A_OFF + s*ASTG);
        const uint32_t* Bs = (const uint32_t*)(sm + B_OFF + s*BSTG);
        #pragma unroll
        for (int ks = 0; ks < 4; ks++) {
            int k0 = ks*8;
            uint32_t af[2][4], bf[4][2];
            #pragma unroll
            for (int mi = 0; mi < 2; mi++) {
                int r = warp_m*32 + mi*16 + g;
                af[mi][0] = As[swz(r,     k0 + t)];
                af[mi][1] = As[swz(r + 8, k0 + t)];
                af[mi][2] = As[swz(r,     k0 + t + 4)];
                af[mi][3] = As[swz(r + 8, k0 + t + 4)];
            }
            #pragma unroll
            for (int ni = 0; ni < 4; ni++) {
                int r = warp_n*32 + ni*8 + g;
                bf[ni][0] = Bs[swz(r, k0 + t)];
                bf[ni][1] = Bs[swz(r, k0 + t + 4)];
            }
            #pragma unroll
            for (int mi = 0; mi < 2; mi++)
                #pragma unroll
                for (int ni = 0; ni < 4; ni++)
                    mma8(acc[mi][ni], af[mi], bf[ni]);
        }
        __syncthreads();
        if (c + 1 < NC) {
            float* Aw = (float*)(sm + A_OFF + (s^1)*ASTG);
            float* Bw = (float*)(sm + B_OFF + (s^1)*BSTG);
            #pragma unroll
            for (int q = 0; q < 4; q++)
                ((float4*)Aw)[(a_row<<3) + ((a_seg*4 + q) ^ (a_row & 7))] = cv4(va[q]);
            #pragma unroll
            for (int q = 0; q < 2; q++)
                ((float4*)Bw)[(b_row<<3) + ((b_seg*2 + q) ^ (b_row & 7))] = cv4(vb[q]);
        }
        __syncthreads();
    }

    // stage D[128][64] (stride 66) — overlaps A/B buffers, already synced
    float* stage = (float*)sm;
    #pragma unroll
    for (int mi = 0; mi < 2; mi++)
        #pragma unroll
        for (int ni = 0; ni < 4; ni++) {
            int r = warp_m*32 + mi*16 + g;
            int cc = warp_n*32 + ni*8 + 2*t;
            stage[r*STG_STRIDE + cc]       = acc[mi][ni][0];
            stage[r*STG_STRIDE + cc + 1]   = acc[mi][ni][1];
            stage[(r+8)*STG_STRIDE + cc]   = acc[mi][ni][2];
            stage[(r+8)*STG_STRIDE + cc+1] = acc[mi][ni][3];
        }
    __syncthreads();

    // drain: row = tid>>1, 16 pairs per thread
    int row = tid >> 1, seg = tid & 1;
    float tr[16];
    #pragma unroll
    for (int r = 0; r < 16; r++) tr[r] = tsm[row*16 + r];
    float buf[16];
    #pragma unroll
    for (int p = 0; p < 16; p++) {
        int jp = seg*16 + p;
        float l0 = 0.f, l1 = 0.f;
        #pragma unroll
        for (int r = 0; r < 16; r++) {
            l0 += tr[r]*lb[jp*16 + r];
            l1 += tr[r]*lb[(32 + jp)*16 + r];
        }
        float u1 = stage[row*STG_STRIDE + jp]      + LSCALE*l0;
        float u2 = stage[row*STG_STRIDE + 32 + jp] + LSCALE*l1;
        float ge = 0.5f*u1*(1.0f + erff(u1*0.7071067811865476f));
        buf[p] = ge*u2;
    }
    if (m0 + row < cnt) {
        float* dst = g_act + (size_t)ls[row]*HID + j0 + seg*16;
        #pragma unroll
        for (int i = 0; i < 4; i++)
            ((float4*)dst)[i] = make_float4(buf[i*4], buf[i*4+1], buf[i*4+2], buf[i*4+3]);
    }
}

// ---------------- down GEMM (tf32 mma.sync) + LoRA + routed weight ----------------
__global__ __launch_bounds__(256, 2)
void k_down_tc(const float* __restrict__ tw, const float* __restrict__ w_down,
               const float* __restrict__ down_b) {
    int e = blockIdx.z, cnt = g_cnt[e];
    int m0 = blockIdx.y * 128;
    if (m0 >= cnt) return;
    int d0 = blockIdx.x * 64;

    extern __shared__ __align__(16) char sm[];
    int tid = threadIdx.x, wid = tid >> 5, lid = tid & 31;

    int* ls = (int*)(sm + LS_OFF);
    float* twsm = (float*)(sm + TW_OFF);
    if (tid < 128) {
        int m = m0 + tid;
        int nk = g_list[e*NKTOT + ((m < cnt) ? m : 0)];
        ls[tid] = nk;
        twsm[tid] = tw[nk];
    }
    __syncthreads();

    float* tsm = (float*)(sm + T_OFF);
    float* lb  = (float*)(sm + LB_OFF);
    {
        const float* Bdn = down_b + (size_t)e*DIM*RNK;
        #pragma unroll
        for (int q = 0; q < 2; q++) {
            int f = tid*2 + q;
            int row = f >> 2, r4 = f & 3;
            ((float4*)tsm)[f] = ((const float4*)(g_t2 + (size_t)ls[row]*RNK))[r4];
        }
        int row = tid >> 2, r4 = tid & 3;
        ((float4*)lb)[tid] = ((const float4*)(Bdn + (size_t)(d0 + row)*RNK))[r4];
    }
    __syncthreads();

    int a_row = tid >> 1, a_seg = tid & 1;
    const float* ap = g_act + (size_t)ls[a_row]*HID + a_seg*16;
    const float* W  = w_down + (size_t)e*DIM*(size_t)HID;
    int b_row = tid >> 2, b_seg = tid & 3;
    const float* bp = W + (size_t)(d0 + b_row)*HID + b_seg*8;

    float4 va[4], vb[2];
    #pragma unroll
    for (int q = 0; q < 4; q++) va[q] = ((const float4*)ap)[q];
    #pragma unroll
    for (int q = 0; q < 2; q++) vb[q] = ((const float4*)bp)[q];
    {
        float* As = (float*)(sm + A_OFF);
        float* Bs = (float*)(sm + B_OFF);
        #pragma unroll
        for (int q = 0; q < 4; q++)
            ((float4*)As)[(a_row<<3) + ((a_seg*4 + q) ^ (a_row & 7))] = cv4(va[q]);
        #pragma unroll
        for (int q = 0; q < 2; q++)
            ((float4*)Bs)[(b_row<<3) + ((b_seg*2 + q) ^ (b_row & 7))] = cv4(vb[q]);
    }
    __syncthreads();

    int warp_m = wid & 3, warp_n = wid >> 2;
    int g = lid >> 2, t = lid & 3;
    float acc[2][4][4];
    #pragma unroll
    for (int mi = 0; mi < 2; mi++)
        #pragma unroll
        for (int ni = 0; ni < 4; ni++)
            #pragma unroll
            for (int q = 0; q < 4; q++) acc[mi][ni][q] = 0.f;

    const int NC = HID/32;
    for (int c = 0; c < NC; c++) {
        int s = c & 1;
        if (c + 1 < NC) {
            #pragma unroll
            for (int q = 0; q < 4; q++) va[q] = ((const float4*)(ap + (c+1)*32))[q];
            #pragma unroll
            for (int q = 0; q < 2; q++) vb[q] = ((const float4*)(bp + (c+1)*32))[q];
        }
        const uint32_t* As = (const uint32_t*)(sm + A_OFF + s*ASTG);
        const uint32_t* Bs = (const uint32_t*)(sm + B_OFF + s*BSTG);
        #pragma unroll
        for (int ks = 0; ks < 4; ks++) {
            int k0 = ks*8;
            uint32_t af[2][4], bf[4][2];
            #pragma unroll
            for (int mi = 0; mi < 2; mi++) {
                int r = warp_m*32 + mi*16 + g;
                af[mi][0] = As[swz(r,     k0 + t)];
                af[mi][1] = As[swz(r + 8, k0 + t)];
                af[mi][2] = As[swz(r,     k0 + t + 4)];
                af[mi][3] = As[swz(r + 8, k0 + t + 4)];
            }
            #pragma unroll
            for (int ni = 0; ni < 4; ni++) {
                int r = warp_n*32 + ni*8 + g;
                bf[ni][0] = Bs[swz(r, k0 + t)];
                bf[ni][1] = Bs[swz(r, k0 + t + 4)];
            }
            #pragma unroll
            for (int mi = 0; mi < 2; mi++)
                #pragma unroll
                for (int ni = 0; ni < 4; ni++)
                    mma8(acc[mi][ni], af[mi], bf[ni]);
        }
        __syncthreads();
        if (c + 1 < NC) {
            float* Aw = (float*)(sm + A_OFF + (s^1)*ASTG);
            float* Bw = (float*)(sm + B_OFF + (s^1)*BSTG);
            #pragma unroll
            for (int q = 0; q < 4; q++)
                ((float4*)Aw)[(a_row<<3) + ((a_seg*4 + q) ^ (a_row & 7))] = cv4(va[q]);
            #pragma unroll
            for (int q = 0; q < 2; q++)
                ((float4*)Bw)[(b_row<<3) + ((b_seg*2 + q) ^ (b_row & 7))] = cv4(vb[q]);
        }
        __syncthreads();
    }

    float* stage = (float*)sm;
    #pragma unroll
    for (int mi = 0; mi < 2; mi++)
        #pragma unroll
        for (int ni = 0; ni < 4; ni++) {
            int r = warp_m*32 + mi*16 + g;
            int cc = warp_n*32 + ni*8 + 2*t;
            stage[r*STG_STRIDE + cc]       = acc[mi][ni][0];
            stage[r*STG_STRIDE + cc + 1]   = acc[mi][ni][1];
            stage[(r+8)*STG_STRIDE + cc]   = acc[mi][ni][2];
            stage[(r+8)*STG_STRIDE + cc+1] = acc[mi][ni][3];
        }
    __syncthreads();

    int row = tid >> 1, seg = tid & 1;
    float tr[16];
    #pragma unroll
    for (int r = 0; r < 16; r++) tr[r] = tsm[row*16 + r];
    float twv = twsm[row];
    float buf[32];
    #pragma unroll
    for (int ci = 0; ci < 32; ci++) {
        int col = seg*32 + ci;
        float l = 0.f;
        #pragma unroll
        for (int r = 0; r < 16; r++) l += tr[r]*lb[col*16 + r];
        buf[ci] = (stage[row*STG_STRIDE + col] + LSCALE*l) * twv;
    }
    if (m0 + row < cnt) {
        float* dst = g_down + (size_t)ls[row]*DIM + d0 + seg*32;
        #pragma unroll
        for (int i = 0; i < 8; i++)
            ((float4*)dst)[i] = make_float4(buf[i*4], buf[i*4+1], buf[i*4+2], buf[i*4+3]);
    }
}

// ---------------- deterministic k-sum ----------------
__global__ void k_combine(float* __restrict__ out) {
    int idx = blockIdx.x*blockDim.x + threadIdx.x;
    if (idx < N_TOK*DIM/4) {
        int n    = idx / (DIM/4);
        int rest = idx - n*(DIM/4);
        const float4* a = (const float4*)g_down + (size_t)(2*n)*(DIM/4) + rest;
        const float4* b = a + (DIM/4);
        float4 va = *a, vb = *b;
        ((float4*)out)[idx] = make_float4(va.x+vb.x, va.y+vb.y, va.z+vb.z, va.w+vb.w);
    }
}

// ---------------- launch ----------------
extern "C" void kernel_launch(void* const* d_in, const int* in_sizes, int n_in,
                              void* d_out, int out_size) {
    const float* x      = (const float*)d_in[0];
    const float* tw     = (const float*)d_in[1];
    const int*   ids    = (const int*)  d_in[2];
    const float* w_up   = (const float*)d_in[3];
    const float* w_down = (const float*)d_in[4];
    const float* up_a   = (const float*)d_in[5];
    const float* up_b   = (const float*)d_in[6];
    const float* down_a = (const float*)d_in[7];
    const float* down_b = (const float*)d_in[8];
    float* out = (float*)d_out;
    (void)in_sizes; (void)n_in; (void)out_size;

    cudaFuncSetAttribute(k_up_tc,   cudaFuncAttributeMaxDynamicSharedMemorySize, SMEM_BYTES);
    cudaFuncSetAttribute(k_down_tc, cudaFuncAttributeMaxDynamicSharedMemorySize, SMEM_BYTES);

    k_zero<<<1, 32>>>();
    k_route<<<(NKTOT+255)/256, 256>>>(ids);
    k_t_up<<<NKTOT, 128>>>(x, ids, up_a);
    k_up_tc<<<dim3(HID/32, NKTOT/128, NEXP), 256, SMEM_BYTES>>>(x, w_up, up_b);
    k_t_down<<<NKTOT, 128>>>(ids, down_a);
    k_down_tc<<<dim3(DIM/64, NKTOT/128, NEXP), 256, SMEM_BYTES>>>(tw, w_down, down_b);
    k_combine<<<(N_TOK*DIM/4 + 255)/256, 256>>>(out);
}

// round 4
// speedup vs baseline: 2.0950x; 1.0788x over previous
#include <cuda_runtime.h>
#include <math.h>
#include <cstdint>

#define N_TOK 1024
#define TOPK  2
#define NEXP  16
#define HID   1024
#define DIM   2048
#define RNK   16
#define NKTOT (N_TOK*TOPK)
#define LSCALE 0.25f

// ---------------- scratch (static device globals; no allocation) ----------------
__device__ int   g_cnt[NEXP];
__device__ int   g_list[NEXP*NKTOT];
__device__ __align__(16) float g_t[NKTOT*RNK];
__device__ __align__(16) float g_t2[NKTOT*RNK];
__device__ __align__(16) float g_act[(size_t)NKTOT*HID];
__device__ __align__(16) float g_down[(size_t)NKTOT*DIM];

// ---------------- helpers ----------------
__device__ __forceinline__ uint32_t smem_u32(const void* p){
    uint32_t a;
    asm("{ .reg .u64 t; cvta.to.shared.u64 t, %1; cvt.u32.u64 %0, t; }":"=r"(a):"l"(p));
    return a;
}
__device__ __forceinline__ float totf(float x){
    uint32_t u; asm("cvt.rna.tf32.f32 %0, %1;" : "=r"(u) : "f"(x));
    return __uint_as_float(u);
}
__device__ __forceinline__ float4 cv4(float4 v){
    return make_float4(totf(v.x), totf(v.y), totf(v.z), totf(v.w));
}
__device__ __forceinline__ void mma8(float* c, const uint32_t* a, const uint32_t* b){
    asm volatile("mma.sync.aligned.m16n8k8.row.col.f32.tf32.tf32.f32 "
        "{%0,%1,%2,%3}, {%4,%5,%6,%7}, {%8,%9}, {%0,%1,%2,%3};"
        : "+f"(c[0]), "+f"(c[1]), "+f"(c[2]), "+f"(c[3])
        : "r"(a[0]), "r"(a[1]), "r"(a[2]), "r"(a[3]), "r"(b[0]), "r"(b[1]));
}
__device__ __forceinline__ void ldsm4(uint32_t* r, uint32_t addr){
    asm volatile("ldmatrix.sync.aligned.m8n8.x4.shared.b16 {%0,%1,%2,%3}, [%4];"
        : "=r"(r[0]), "=r"(r[1]), "=r"(r[2]), "=r"(r[3]) : "r"(addr));
}

// smem layout (dynamic)
#define ASTG 16384u
#define BSTG 8192u
#define A_OFF 0u
#define B_OFF 32768u
#define LB_OFF 49152u
#define T_OFF 53248u
#define LS_OFF 61440u
#define TW_OFF 61952u
#define SMEM_BYTES 62464
#define STG_STRIDE 66           // epilogue stage row stride in floats

// ---------------- routing ----------------
__global__ void k_zero() { if (threadIdx.x < NEXP) g_cnt[threadIdx.x] = 0; }

__global__ void k_route(const int* __restrict__ ids) {
    int nk = blockIdx.x*blockDim.x + threadIdx.x;
    if (nk < NKTOT) {
        int e = ids[nk];
        int p = atomicAdd(&g_cnt[e], 1);
        g_list[e*NKTOT + p] = nk;
    }
}

// ---------------- LoRA t vectors ----------------
__global__ void k_t_up(const float* __restrict__ x, const int* __restrict__ ids,
                       const float* __restrict__ up_a) {
    int nk = blockIdx.x;
    int n  = nk / TOPK;
    int e  = ids[nk];
    int warp = threadIdx.x >> 5, lane = threadIdx.x & 31;
    const float4* xr = (const float4*)(x + (size_t)n*DIM);
    const float4* A  = (const float4*)(up_a + (size_t)e*RNK*DIM);
    #pragma unroll
    for (int rr = 0; rr < 4; rr++) {
        int r = warp*4 + rr;
        const float4* ar = A + (size_t)r*(DIM/4);
        float s = 0.f;
        for (int i = lane; i < DIM/4; i += 32) {
            float4 xv = xr[i], av = ar[i];
            s += xv.x*av.x + xv.y*av.y + xv.z*av.z + xv.w*av.w;
        }
        #pragma unroll
        for (int o = 16; o > 0; o >>= 1) s += __shfl_xor_sync(0xffffffffu, s, o);
        if (lane == 0) g_t[nk*RNK + r] = s;
    }
}

__global__ void k_t_down(const int* __restrict__ ids, const float* __restrict__ down_a) {
    int nk = blockIdx.x;
    int e  = ids[nk];
    int warp = threadIdx.x >> 5, lane = threadIdx.x & 31;
    const float4* xr = (const float4*)(g_act + (size_t)nk*HID);
    const float4* A  = (const float4*)(down_a + (size_t)e*RNK*HID);
    #pragma unroll
    for (int rr = 0; rr < 4; rr++) {
        int r = warp*4 + rr;
        const float4* ar = A + (size_t)r*(HID/4);
        float s = 0.f;
        for (int i = lane; i < HID/4; i += 32) {
            float4 xv = xr[i], av = ar[i];
            s += xv.x*av.x + xv.y*av.y + xv.z*av.z + xv.w*av.w;
        }
        #pragma unroll
        for (int o = 16; o > 0; o >>= 1) s += __shfl_xor_sync(0xffffffffu, s, o);
        if (lane == 0) g_t2[nk*RNK + r] = s;
    }
}

// ---------------- up GEMM (tf32 mma.sync + ldmatrix) + LoRA + gelu*mul ----------------
__global__ __launch_bounds__(256, 2)
void k_up_tc(const float* __restrict__ x, const float* __restrict__ w_up,
             const float* __restrict__ up_b) {
    int e = blockIdx.z, cnt = g_cnt[e];
    int m0 = blockIdx.y * 128;
    if (m0 >= cnt) return;
    int j0 = blockIdx.x * 32;

    extern __shared__ __align__(16) char sm[];
    uint32_t sbase = smem_u32(sm);
    int tid = threadIdx.x, wid = tid >> 5, lid = tid & 31;

    int* ls = (int*)(sm + LS_OFF);
    if (tid < 128) {
        int m = m0 + tid;
        ls[tid] = g_list[e*NKTOT + ((m < cnt) ? m : 0)];
    }
    __syncthreads();

    float* tsm = (float*)(sm + T_OFF);
    float* lb  = (float*)(sm + LB_OFF);
    {
        const float* Bup = up_b + (size_t)e*(2*HID)*RNK;
        #pragma unroll
        for (int q = 0; q < 2; q++) {
            int f = tid*2 + q;
            int row = f >> 2, r4 = f & 3;
            ((float4*)tsm)[f] = ((const float4*)(g_t + (size_t)ls[row]*RNK))[r4];
        }
        int row = tid >> 2, r4 = tid & 3;
        int grow = (row < 32) ? (j0 + row) : (HID + j0 + row - 32);
        ((float4*)lb)[tid] = ((const float4*)(Bup + (size_t)grow*RNK))[r4];
    }
    __syncthreads();

    // producers
    int a_row = tid >> 1, a_seg = tid & 1;
    const float* ap = x + (size_t)(ls[a_row] >> 1)*DIM + a_seg*16;
    const float* W  = w_up + (size_t)e*(2*HID)*(size_t)DIM;
    int b_row = tid >> 2, b_seg = tid & 3;
    int bgrow = (b_row < 32) ? (j0 + b_row) : (HID + j0 + b_row - 32);
    const float* bp = W + (size_t)bgrow*DIM + b_seg*8;

    float4 va[4], vb[2];
    #pragma unroll
    for (int q = 0; q < 4; q++) va[q] = ((const float4*)ap)[q];
    #pragma unroll
    for (int q = 0; q < 2; q++) vb[q] = ((const float4*)bp)[q];
    {
        float* As = (float*)(sm + A_OFF);
        float* Bs = (float*)(sm + B_OFF);
        #pragma unroll
        for (int q = 0; q < 4; q++)
            ((float4*)As)[(a_row<<3) + ((a_seg*4 + q) ^ (a_row & 7))] = cv4(va[q]);
        #pragma unroll
        for (int q = 0; q < 2; q++)
            ((float4*)Bs)[(b_row<<3) + ((b_seg*2 + q) ^ (b_row & 7))] = cv4(vb[q]);
    }
    __syncthreads();

    int warp_m = wid & 3, warp_n = wid >> 2;
    // ldmatrix per-thread source rows (16B-unit granularity)
    int rsub    = lid & 7;
    int mat_lo  = (lid >> 3) & 1;       // A: +8 rows   | B: +1 q
    int mat_hi  = (lid >> 4) & 1;       // A: +1 q      | B: +8 rows
    int arow_l  = warp_m*32 + mat_lo*8 + rsub;          // + mi*16
    int brow_l  = warp_n*32 + mat_hi*8 + rsub;          // + p*16

    float acc[2][4][4];
    #pragma unroll
    for (int mi = 0; mi < 2; mi++)
        #pragma unroll
        for (int ni = 0; ni < 4; ni++)
            #pragma unroll
            for (int q = 0; q < 4; q++) acc[mi][ni][q] = 0.f;

    const int NC = DIM/32;
    for (int c = 0; c < NC; c++) {
        int s = c & 1;
        if (c + 1 < NC) {
            #pragma unroll
            for (int q = 0; q < 4; q++) va[q] = ((const float4*)(ap + (c+1)*32))[q];
            #pragma unroll
            for (int q = 0; q < 2; q++) vb[q] = ((const float4*)(bp + (c+1)*32))[q];
        }
        uint32_t Ab = sbase + A_OFF + s*ASTG;
        uint32_t Bb = sbase + B_OFF + s*BSTG;
        #pragma unroll
        for (int ks = 0; ks < 4; ks++) {
            uint32_t af[2][4], bf[4][2];
            #pragma unroll
            for (int mi = 0; mi < 2; mi++) {
                int r = arow_l + mi*16;
                int q = 2*ks + mat_hi;
                ldsm4(af[mi], Ab + (r << 7) + (((q ^ (r & 7)) & 7) << 4));
            }
            #pragma unroll
            for (int p = 0; p < 2; p++) {
                int r = brow_l + p*16;
                int q = 2*ks + mat_lo;
                uint32_t t4[4];
                ldsm4(t4, Bb + (r << 7) + (((q ^ (r & 7)) & 7) << 4));
                bf[2*p][0]   = t4[0]; bf[2*p][1]   = t4[1];
                bf[2*p+1][0] = t4[2]; bf[2*p+1][1] = t4[3];
            }
            #pragma unroll
            for (int mi = 0; mi < 2; mi++)
                #pragma unroll
                for (int ni = 0; ni < 4; ni++)
                    mma8(acc[mi][ni], af[mi], bf[ni]);
        }
        __syncthreads();
        if (c + 1 < NC) {
            float* Aw = (float*)(sm + A_OFF + (s^1)*ASTG);
            float* Bw = (float*)(sm + B_OFF + (s^1)*BSTG);
            #pragma unroll
            for (int q = 0; q < 4; q++)
                ((float4*)Aw)[(a_row<<3) + ((a_seg*4 + q) ^ (a_row & 7))] = cv4(va[q]);
            #pragma unroll
            for (int q = 0; q < 2; q++)
                ((float4*)Bw)[(b_row<<3) + ((b_seg*2 + q) ^ (b_row & 7))] = cv4(vb[q]);
        }
        __syncthreads();
    }

    // stage D[128][64] (stride 66) — overlaps A/B buffers, already synced
    int g = lid >> 2, t = lid & 3;
    float* stage = (float*)sm;
    #pragma unroll
    for (int mi = 0; mi < 2; mi++)
        #pragma unroll
        for (int ni = 0; ni < 4; ni++) {
            int r = warp_m*32 + mi*16 + g;
            int cc = warp_n*32 + ni*8 + 2*t;
            stage[r*STG_STRIDE + cc]       = acc[mi][ni][0];
            stage[r*STG_STRIDE + cc + 1]   = acc[mi][ni][1];
            stage[(r+8)*STG_STRIDE + cc]   = acc[mi][ni][2];
            stage[(r+8)*STG_STRIDE + cc+1] = acc[mi][ni][3];
        }
    __syncthreads();

    int row = tid >> 1, seg = tid & 1;
    float tr[16];
    #pragma unroll
    for (int r = 0; r < 16; r++) tr[r] = tsm[row*16 + r];
    float buf[16];
    #pragma unroll
    for (int p = 0; p < 16; p++) {
        int jp = seg*16 + p;
        float l0 = 0.f, l1 = 0.f;
        #pragma unroll
        for (int r = 0; r < 16; r++) {
            l0 += tr[r]*lb[jp*16 + r];
            l1 += tr[r]*lb[(32 + jp)*16 + r];
        }
        float u1 = stage[row*STG_STRIDE + jp]      + LSCALE*l0;
        float u2 = stage[row*STG_STRIDE + 32 + jp] + LSCALE*l1;
        float ge = 0.5f*u1*(1.0f + erff(u1*0.7071067811865476f));
        buf[p] = ge*u2;
    }
    if (m0 + row < cnt) {
        float* dst = g_act + (size_t)ls[row]*HID + j0 + seg*16;
        #pragma unroll
        for (int i = 0; i < 4; i++)
            ((float4*)dst)[i] = make_float4(buf[i*4], buf[i*4+1], buf[i*4+2], buf[i*4+3]);
    }
}

// ---------------- down GEMM (tf32 mma.sync + ldmatrix) + LoRA + routed weight ----------------
__global__ __launch_bounds__(256, 2)
void k_down_tc(const float* __restrict__ tw, const float* __restrict__ w_down,
               const float* __restrict__ down_b) {
    int e = blockIdx.z, cnt = g_cnt[e];
    int m0 = blockIdx.y * 128;
    if (m0 >= cnt) return;
    int d0 = blockIdx.x * 64;

    extern __shared__ __align__(16) char sm[];
    uint32_t sbase = smem_u32(sm);
    int tid = threadIdx.x, wid = tid >> 5, lid = tid & 31;

    int* ls = (int*)(sm + LS_OFF);
    float* twsm = (float*)(sm + TW_OFF);
    if (tid < 128) {
        int m = m0 + tid;
        int nk = g_list[e*NKTOT + ((m < cnt) ? m : 0)];
        ls[tid] = nk;
        twsm[tid] = tw[nk];
    }
    __syncthreads();

    float* tsm = (float*)(sm + T_OFF);
    float* lb  = (float*)(sm + LB_OFF);
    {
        const float* Bdn = down_b + (size_t)e*DIM*RNK;
        #pragma unroll
        for (int q = 0; q < 2; q++) {
            int f = tid*2 + q;
            int row = f >> 2, r4 = f & 3;
            ((float4*)tsm)[f] = ((const float4*)(g_t2 + (size_t)ls[row]*RNK))[r4];
        }
        int row = tid >> 2, r4 = tid & 3;
        ((float4*)lb)[tid] = ((const float4*)(Bdn + (size_t)(d0 + row)*RNK))[r4];
    }
    __syncthreads();

    int a_row = tid >> 1, a_seg = tid & 1;
    const float* ap = g_act + (size_t)ls[a_row]*HID + a_seg*16;
    const float* W  = w_down + (size_t)e*DIM*(size_t)HID;
    int b_row = tid >> 2, b_seg = tid & 3;
    const float* bp = W + (size_t)(d0 + b_row)*HID + b_seg*8;

    float4 va[4], vb[2];
    #pragma unroll
    for (int q = 0; q < 4; q++) va[q] = ((const float4*)ap)[q];
    #pragma unroll
    for (int q = 0; q < 2; q++) vb[q] = ((const float4*)bp)[q];
    {
        float* As = (float*)(sm + A_OFF);
        float* Bs = (float*)(sm + B_OFF);
        #pragma unroll
        for (int q = 0; q < 4; q++)
            ((float4*)As)[(a_row<<3) + ((a_seg*4 + q) ^ (a_row & 7))] = cv4(va[q]);
        #pragma unroll
        for (int q = 0; q < 2; q++)
            ((float4*)Bs)[(b_row<<3) + ((b_seg*2 + q) ^ (b_row & 7))] = cv4(vb[q]);
    }
    __syncthreads();

    int warp_m = wid & 3, warp_n = wid >> 2;
    int rsub   = lid & 7;
    int mat_lo = (lid >> 3) & 1;
    int mat_hi = (lid >> 4) & 1;
    int arow_l = warp_m*32 + mat_lo*8 + rsub;
    int brow_l = warp_n*32 + mat_hi*8 + rsub;

    float acc[2][4][4];
    #pragma unroll
    for (int mi = 0; mi < 2; mi++)
        #pragma unroll
        for (int ni = 0; ni < 4; ni++)
            #pragma unroll
            for (int q = 0; q < 4; q++) acc[mi][ni][q] = 0.f;

    const int NC = HID/32;
    for (int c = 0; c < NC; c++) {
        int s = c & 1;
        if (c + 1 < NC) {
            #pragma unroll
            for (int q = 0; q < 4; q++) va[q] = ((const float4*)(ap + (c+1)*32))[q];
            #pragma unroll
            for (int q = 0; q < 2; q++) vb[q] = ((const float4*)(bp + (c+1)*32))[q];
        }
        uint32_t Ab = sbase + A_OFF + s*ASTG;
        uint32_t Bb = sbase + B_OFF + s*BSTG;
        #pragma unroll
        for (int ks = 0; ks < 4; ks++) {
            uint32_t af[2][4], bf[4][2];
            #pragma unroll
            for (int mi = 0; mi < 2; mi++) {
                int r = arow_l + mi*16;
                int q = 2*ks + mat_hi;
                ldsm4(af[mi], Ab + (r << 7) + (((q ^ (r & 7)) & 7) << 4));
            }
            #pragma unroll
            for (int p = 0; p < 2; p++) {
                int r = brow_l + p*16;
                int q = 2*ks + mat_lo;
                uint32_t t4[4];
                ldsm4(t4, Bb + (r << 7) + (((q ^ (r & 7)) & 7) << 4));
                bf[2*p][0]   = t4[0]; bf[2*p][1]   = t4[1];
                bf[2*p+1][0] = t4[2]; bf[2*p+1][1] = t4[3];
            }
            #pragma unroll
            for (int mi = 0; mi < 2; mi++)
                #pragma unroll
                for (int ni = 0; ni < 4; ni++)
                    mma8(acc[mi][ni], af[mi], bf[ni]);
        }
        __syncthreads();
        if (c + 1 < NC) {
            float* Aw = (float*)(sm + A_OFF + (s^1)*ASTG);
            float* Bw = (float*)(sm + B_OFF + (s^1)*BSTG);
            #pragma unroll
            for (int q = 0; q < 4; q++)
                ((float4*)Aw)[(a_row<<3) + ((a_seg*4 + q) ^ (a_row & 7))] = cv4(va[q]);
            #pragma unroll
            for (int q = 0; q < 2; q++)
                ((float4*)Bw)[(b_row<<3) + ((b_seg*2 + q) ^ (b_row & 7))] = cv4(vb[q]);
        }
        __syncthreads();
    }

    int g = lid >> 2, t = lid & 3;
    float* stage = (float*)sm;
    #pragma unroll
    for (int mi = 0; mi < 2; mi++)
        #pragma unroll
        for (int ni = 0; ni < 4; ni++) {
            int r = warp_m*32 + mi*16 + g;
            int cc = warp_n*32 + ni*8 + 2*t;
            stage[r*STG_STRIDE + cc]       = acc[mi][ni][0];
            stage[r*STG_STRIDE + cc + 1]   = acc[mi][ni][1];
            stage[(r+8)*STG_STRIDE + cc]   = acc[mi][ni][2];
            stage[(r+8)*STG_STRIDE + cc+1] = acc[mi][ni][3];
        }
    __syncthreads();

    int row = tid >> 1, seg = tid & 1;
    float tr[16];
    #pragma unroll
    for (int r = 0; r < 16; r++) tr[r] = tsm[row*16 + r];
    float twv = twsm[row];
    float buf[32];
    #pragma unroll
    for (int ci = 0; ci < 32; ci++) {
        int col = seg*32 + ci;
        float l = 0.f;
        #pragma unroll
        for (int r = 0; r < 16; r++) l += tr[r]*lb[col*16 + r];
        buf[ci] = (stage[row*STG_STRIDE + col] + LSCALE*l) * twv;
    }
    if (m0 + row < cnt) {
        float* dst = g_down + (size_t)ls[row]*DIM + d0 + seg*32;
        #pragma unroll
        for (int i = 0; i < 8; i++)
            ((float4*)dst)[i] = make_float4(buf[i*4], buf[i*4+1], buf[i*4+2], buf[i*4+3]);
    }
}

// ---------------- deterministic k-sum ----------------
__global__ void k_combine(float* __restrict__ out) {
    int idx = blockIdx.x*blockDim.x + threadIdx.x;
    if (idx < N_TOK*DIM/4) {
        int n    = idx / (DIM/4);
        int rest = idx - n*(DIM/4);
        const float4* a = (const float4*)g_down + (size_t)(2*n)*(DIM/4) + rest;
        const float4* b = a + (DIM/4);
        float4 va = *a, vb = *b;
        ((float4*)out)[idx] = make_float4(va.x+vb.x, va.y+vb.y, va.z+vb.z, va.w+vb.w);
    }
}

// ---------------- launch ----------------
extern "C" void kernel_launch(void* const* d_in, const int* in_sizes, int n_in,
                              void* d_out, int out_size) {
    const float* x      = (const float*)d_in[0];
    const float* tw     = (const float*)d_in[1];
    const int*   ids    = (const int*)  d_in[2];
    const float* w_up   = (const float*)d_in[3];
    const float* w_down = (const float*)d_in[4];
    const float* up_a   = (const float*)d_in[5];
    const float* up_b   = (const float*)d_in[6];
    const float* down_a = (const float*)d_in[7];
    const float* down_b = (const float*)d_in[8];
    float* out = (float*)d_out;
    (void)in_sizes; (void)n_in; (void)out_size;

    cudaFuncSetAttribute(k_up_tc,   cudaFuncAttributeMaxDynamicSharedMemorySize, SMEM_BYTES);
    cudaFuncSetAttribute(k_down_tc, cudaFuncAttributeMaxDynamicSharedMemorySize, SMEM_BYTES);

    k_zero<<<1, 32>>>();
    k_route<<<(NKTOT+255)/256, 256>>>(ids);
    k_t_up<<<NKTOT, 128>>>(x, ids, up_a);
    k_up_tc<<<dim3(HID/32, NKTOT/128, NEXP), 256, SMEM_BYTES>>>(x, w_up, up_b);
    k_t_down<<<NKTOT, 128>>>(ids, down_a);
    k_down_tc<<<dim3(DIM/64, NKTOT/128, NEXP), 256, SMEM_BYTES>>>(tw, w_down, down_b);
    k_combine<<<(N_TOK*DIM/4 + 255)/256, 256>>>(out);
}